// round 9
// baseline (speedup 1.0000x reference)
#include <cuda_runtime.h>
#include <cstdint>

#define NN 50000
#define EE 800000
#define HB 256          // histogram blocks inside prep kernel
#define NB 782          // node blocks per type: ceil(50000/64)

typedef unsigned long long u64;

// ---------------- scratch (device globals; no allocation allowed) ----------------
__device__ __align__(16) float g_sq_a[NN * 2];
__device__ __align__(16) float g_sk_a[NN * 2];
__device__ __align__(16) float g_sq_b[NN * 2];
__device__ __align__(16) float g_sk_b[NN * 2];
__device__ __align__(16) float g_v1[NN * 64];     // v_a + rel1 (natural col order)
__device__ __align__(16) float g_v2[NN * 64];     // v_b + rel2
__device__ __align__(16) float g_agg1[NN * 64];   // normalized agg, dst = b
__device__ __align__(16) float g_agg2[NN * 64];   // dst = a
__device__ int g_cnt1[NN],     g_cnt2[NN];
__device__ int g_off1[NN + 1], g_off2[NN + 1];
__device__ int g_cur1[NN],     g_cur2[NN];
__device__ __align__(16) u64 g_pair1[EE];         // (e << 32) | row[e]
__device__ __align__(16) u64 g_pair2[EE];

// ---------------- helpers ----------------
__device__ __forceinline__ float tanh_fast(float x) {
    float y;
    asm("tanh.approx.f32 %0, %1;" : "=f"(y) : "f"(x));
    return y;
}
__device__ __forceinline__ u64 pack2(float lo, float hi) {
    u64 r;
    asm("mov.b64 %0, {%1, %2};" : "=l"(r) : "f"(lo), "f"(hi));
    return r;
}
__device__ __forceinline__ void unpack2(u64 v, float& lo, float& hi) {
    asm("mov.b64 {%0, %1}, %2;" : "=f"(lo), "=f"(hi) : "l"(v));
}
__device__ __forceinline__ u64 fma2(u64 a, u64 b, u64 c) {
    u64 d;
    asm("fma.rn.f32x2 %0, %1, %2, %3;" : "=l"(d) : "l"(a), "l"(b), "l"(c));
    return d;
}
__device__ __forceinline__ u64 add2(u64 a, u64 b) {
    u64 d;
    asm("add.rn.f32x2 %0, %1, %2;" : "=l"(d) : "l"(a), "l"(b));
    return d;
}

// ---------------- zero counters ----------------
__global__ void zero_cnt_kernel() {
    int i = blockIdx.x * 256 + threadIdx.x;
    if (i < NN) { g_cnt1[i] = 0; g_cnt2[i] = 0; }
}

// ---------------- prep: histogram + fused-QKV node precompute ----------------
// blocks [0,HB): histogram over col1/col2.  [HB, HB+2NB): QKV (64 nodes/block).
#define PREP_SMEM ((4160 + 3 * 4096 + 192) * 4)

__global__ void __launch_bounds__(512, 2) prep_kernel(
    const float* __restrict__ x_a, const float* __restrict__ Wq_a,
    const float* __restrict__ Wk_a, const float* __restrict__ Wv_a,
    const float* __restrict__ x_b, const float* __restrict__ Wq_b,
    const float* __restrict__ Wk_b, const float* __restrict__ Wv_b,
    const float* __restrict__ emb_a, const float* __restrict__ emb_b,
    const float* __restrict__ rel1, const float* __restrict__ rel2,
    const float* __restrict__ a_attn,
    const int* __restrict__ col1, const int* __restrict__ col2)
{
    int b = blockIdx.x;
    int tid = threadIdx.x;

    if (b < HB) {
        const int S = HB * 512;
        for (int k = b * 512 + tid; k < 2 * EE; k += S) {
            if (k < EE) atomicAdd(&g_cnt1[__ldg(col1 + k)], 1);
            else        atomicAdd(&g_cnt2[__ldg(col2 + k - EE)], 1);
        }
        return;
    }
    b -= HB;
    int type = (b >= NB) ? 1 : 0;
    if (type) b -= NB;

    const float* x   = type ? x_b  : x_a;
    const float* Wqg = type ? Wq_b : Wq_a;
    const float* Wkg = type ? Wk_b : Wk_a;
    const float* Wvg = type ? Wv_b : Wv_a;
    const float* emb = type ? emb_b : emb_a;
    const float* rel = type ? rel2 : rel1;
    float* sq   = type ? g_sq_b : g_sq_a;
    float* sk   = type ? g_sk_b : g_sk_a;
    float* vout = type ? g_v2   : g_v1;

    extern __shared__ float sm[];
    float* xs   = sm;              // 64 x 65
    float* Wq   = sm + 4160;
    float* Wk   = Wq + 4096;
    float* Wv   = Wk + 4096;
    float* embS = Wv + 4096;
    float* relS = embS + 64;
    float* aS   = relS + 64;

    int nb = b * 64;

    for (int i = tid; i < 4096; i += 512) {
        int rr = i >> 6, cc = i & 63;
        int n2 = nb + rr;
        xs[rr * 65 + cc] = (n2 < NN) ? __ldg(x + n2 * 64 + cc) : 0.f;
        Wq[i] = __ldg(Wqg + i);
        Wk[i] = __ldg(Wkg + i);
        Wv[i] = __ldg(Wvg + i);
    }
    if (tid < 64) { embS[tid] = emb[tid]; relS[tid] = rel[tid]; aS[tid] = a_attn[tid]; }
    __syncthreads();

    int g = tid >> 4, cg = tid & 15, c0 = cg * 4;   // g: node pair 0..31

    const ulonglong2* WqV = (const ulonglong2*)Wq;
    const ulonglong2* WkV = (const ulonglong2*)Wk;
    const ulonglong2* WvV = (const ulonglong2*)Wv;

    u64 q0a = 0, q0b = 0, q1a = 0, q1b = 0;
    u64 k0a = 0, k0b = 0, k1a = 0, k1b = 0;
    u64 v0a = 0, v0b = 0, v1a = 0, v1b = 0;

#pragma unroll 8
    for (int j = 0; j < 64; j++) {
        ulonglong2 wq = WqV[j * 16 + cg];
        ulonglong2 wk = WkV[j * 16 + cg];
        ulonglong2 wv = WvV[j * 16 + cg];
        float x0 = xs[(g * 2 + 0) * 65 + j];
        float x1 = xs[(g * 2 + 1) * 65 + j];
        u64 x02 = pack2(x0, x0);
        u64 x12 = pack2(x1, x1);
        q0a = fma2(x02, wq.x, q0a); q0b = fma2(x02, wq.y, q0b);
        q1a = fma2(x12, wq.x, q1a); q1b = fma2(x12, wq.y, q1b);
        k0a = fma2(x02, wk.x, k0a); k0b = fma2(x02, wk.y, k0b);
        k1a = fma2(x12, wk.x, k1a); k1b = fma2(x12, wk.y, k1b);
        v0a = fma2(x02, wv.x, v0a); v0b = fma2(x02, wv.y, v0b);
        v1a = fma2(x12, wv.x, v1a); v1b = fma2(x12, wv.y, v1b);
    }

    float aq[8], ak[8], av[8];
    unpack2(q0a, aq[0], aq[1]); unpack2(q0b, aq[2], aq[3]);
    unpack2(q1a, aq[4], aq[5]); unpack2(q1b, aq[6], aq[7]);
    unpack2(k0a, ak[0], ak[1]); unpack2(k0b, ak[2], ak[3]);
    unpack2(k1a, ak[4], ak[5]); unpack2(k1b, ak[6], ak[7]);
    unpack2(v0a, av[0], av[1]); unpack2(v0b, av[2], av[3]);
    unpack2(v1a, av[4], av[5]); unpack2(v1b, av[6], av[7]);

    int n0 = nb + g * 2;

    float pq[2], pk[2];
#pragma unroll
    for (int r = 0; r < 2; r++) {
        float sQ = 0.f, sK = 0.f;
#pragma unroll
        for (int k = 0; k < 4; k++) {
            int c = c0 + k;
            sQ += tanh_fast(aq[r * 4 + k] + embS[c]) * aS[c & 31];
            sK += tanh_fast(ak[r * 4 + k] + embS[c]) * aS[32 + (c & 31)];
        }
        pq[r] = sQ; pk[r] = sK;
    }
#pragma unroll
    for (int m = 1; m < 8; m <<= 1) {
#pragma unroll
        for (int r = 0; r < 2; r++) {
            pq[r] += __shfl_xor_sync(0xffffffffu, pq[r], m);
            pk[r] += __shfl_xor_sync(0xffffffffu, pk[r], m);
        }
    }
    if ((cg & 7) == 0) {
        int h = cg >> 3;
#pragma unroll
        for (int r = 0; r < 2; r++) {
            int n = n0 + r;
            if (n < NN) { sq[n * 2 + h] = pq[r]; sk[n * 2 + h] = pk[r]; }
        }
    }

#pragma unroll
    for (int r = 0; r < 2; r++) {
        int n = n0 + r;
        if (n < NN) {
            *(float4*)(vout + (size_t)n * 64 + c0) =
                make_float4(av[r*4+0] + relS[c0+0], av[r*4+1] + relS[c0+1],
                            av[r*4+2] + relS[c0+2], av[r*4+3] + relS[c0+3]);
        }
    }
}

// ---------------- scan: exclusive prefix over counts -> offsets + cursors ----------------
__global__ void __launch_bounds__(1024) scan_kernel() {
    int rel = blockIdx.x;
    const int* cnt = rel ? g_cnt2 : g_cnt1;
    int* off = rel ? g_off2 : g_off1;
    int* cur = rel ? g_cur2 : g_cur1;
    int t = threadIdx.x;
    const int C = (NN + 1023) / 1024;   // 49
    int s = t * C;
    int e = (s + C < NN) ? s + C : NN;

    int local = 0;
    for (int i = s; i < e; i++) local += cnt[i];

    __shared__ int wsum[32];
    int lane = t & 31, wid = t >> 5;
    int v = local;
#pragma unroll
    for (int m = 1; m < 32; m <<= 1) {
        int u = __shfl_up_sync(0xffffffffu, v, m);
        if (lane >= m) v += u;
    }
    if (lane == 31) wsum[wid] = v;
    __syncthreads();
    if (wid == 0) {
        int wv = wsum[lane];
#pragma unroll
        for (int m = 1; m < 32; m <<= 1) {
            int u = __shfl_up_sync(0xffffffffu, wv, m);
            if (lane >= m) wv += u;
        }
        wsum[lane] = wv;
    }
    __syncthreads();
    int run = v - local + ((wid > 0) ? wsum[wid - 1] : 0);
    for (int i = s; i < e; i++) { off[i] = run; cur[i] = run; run += cnt[i]; }
    if (t == 0) off[NN] = EE;
}

// ---------------- scatter: build (e, row) pairs grouped by dst ----------------
__global__ void __launch_bounds__(256) scatter_kernel(
    const int* __restrict__ row1, const int* __restrict__ col1,
    const int* __restrict__ row2, const int* __restrict__ col2)
{
    const int S = gridDim.x * 256;
    for (int k = blockIdx.x * 256 + threadIdx.x; k < 2 * EE; k += S) {
        if (k < EE) {
            int c = __ldg(col1 + k);
            int pos = atomicAdd(&g_cur1[c], 1);
            g_pair1[pos] = ((u64)(unsigned)k << 32) | (unsigned)__ldg(row1 + k);
        } else {
            int e2 = k - EE;
            int c = __ldg(col2 + e2);
            int pos = atomicAdd(&g_cur2[c], 1);
            g_pair2[pos] = ((u64)(unsigned)e2 << 32) | (unsigned)__ldg(row2 + e2);
        }
    }
}

// ---------------- edge pass (CSR): one warp per destination node ----------------
// 4 edges per warp-iteration (8 lanes each); register accumulation; plain stores.
__global__ void __launch_bounds__(256) edge_csr_kernel(
    const float* __restrict__ ea1, const float* __restrict__ ea2,
    const float* __restrict__ We, const float* __restrict__ a_attn)
{
    __shared__ __align__(16) float WeS[1024];     // [16][64]
    __shared__ float a4S[32];
    int tid = threadIdx.x;
    for (int i = tid; i < 1024; i += 256) WeS[i] = We[i];
    if (tid < 32) a4S[tid] = a_attn[96 + tid];
    __syncthreads();

    int w    = tid >> 5;
    int lane = tid & 31;
    int grp  = lane >> 3, l8 = lane & 7;

    int gd  = blockIdx.x * 8 + w;                 // 0 .. 2*NN-1
    int rel = (gd >= NN) ? 1 : 0;
    int c   = rel ? gd - NN : gd;

    const float* ea   = rel ? ea2    : ea1;
    const int*   off  = rel ? g_off2 : g_off1;
    const u64*   pair = rel ? g_pair2 : g_pair1;
    const float* sq   = rel ? g_sq_a : g_sq_b;    // destination-node q scalar
    const float* sk   = rel ? g_sk_b : g_sk_a;    // source-node k scalar
    const float* vsrc = rel ? g_v2   : g_v1;
    float*       agg  = rel ? g_agg2 : g_agg1;

    int off0 = __ldg(off + c);
    int deg  = __ldg(off + c + 1) - off0;
    float* ap = agg + (size_t)c * 64;

    if (deg == 0) {
        if (grp == 0) {
            const float4 z = make_float4(0.f, 0.f, 0.f, 0.f);
            *(float4*)(ap + 4 * l8) = z;
            *(float4*)(ap + 32 + 4 * l8) = z;
        }
        return;
    }

    float2 sqv = __ldg((const float2*)sq + c);
    const ulonglong2* WeV = (const ulonglong2*)WeS;

    float d0 = 0.f, d1 = 0.f;
    u64 m01 = 0, m23 = 0, m45 = 0, m67 = 0;

    for (int base = 0; base < deg; base += 4) {
        int slot = base + grp;
        bool valid = slot < deg;
        int idx = off0 + (valid ? slot : 0);
        u64 pr = __ldg(pair + idx);
        int r = (int)(unsigned)(pr & 0xffffffffu);
        int e = (int)(unsigned)(pr >> 32);

        const float4* ea4p = (const float4*)ea + (size_t)e * 4;
        float4 A = __ldg(ea4p), B = __ldg(ea4p + 1), C = __ldg(ea4p + 2), D = __ldg(ea4p + 3);
        float ear[16] = {A.x, A.y, A.z, A.w, B.x, B.y, B.z, B.w,
                         C.x, C.y, C.z, C.w, D.x, D.y, D.z, D.w};

        u64 a01 = 0, a23 = 0, a45 = 0, a67 = 0;
#pragma unroll
        for (int j = 0; j < 16; j++) {
            u64 ev2 = pack2(ear[j], ear[j]);
            ulonglong2 w0 = WeV[j * 16 + l8];         // cols 4l..4l+3
            ulonglong2 w1 = WeV[j * 16 + 8 + l8];     // cols 32+4l..32+4l+3
            a01 = fma2(ev2, w0.x, a01);
            a23 = fma2(ev2, w0.y, a23);
            a45 = fma2(ev2, w1.x, a45);
            a67 = fma2(ev2, w1.y, a67);
        }
        float acc[8];
        unpack2(a01, acc[0], acc[1]); unpack2(a23, acc[2], acc[3]);
        unpack2(a45, acc[4], acc[5]); unpack2(a67, acc[6], acc[7]);

        float se0 = 0.f, se1 = 0.f;
#pragma unroll
        for (int t = 0; t < 4; t++) {
            float av = a4S[4 * l8 + t];
            se0 += tanh_fast(acc[t])     * av;
            se1 += tanh_fast(acc[4 + t]) * av;
        }
#pragma unroll
        for (int m = 1; m < 8; m <<= 1) {
            se0 += __shfl_xor_sync(0xffffffffu, se0, m);
            se1 += __shfl_xor_sync(0xffffffffu, se1, m);
        }

        float2 skv = __ldg((const float2*)sk + r);
        float ex0 = valid ? __expf(sqv.x + skv.x + se0) : 0.f;
        float ex1 = valid ? __expf(sqv.y + skv.y + se1) : 0.f;
        d0 += ex0; d1 += ex1;

        const ulonglong2* vp = (const ulonglong2*)(vsrc + (size_t)r * 64);
        ulonglong2 vv0 = __ldg(vp + l8);          // cols 4l..4l+3
        ulonglong2 vv1 = __ldg(vp + 8 + l8);      // cols 32+4l..32+4l+3

        u64 ex0p = pack2(ex0, ex0), ex1p = pack2(ex1, ex1);
        m01 = fma2(ex0p, add2(vv0.x, a01), m01);
        m23 = fma2(ex0p, add2(vv0.y, a23), m23);
        m45 = fma2(ex1p, add2(vv1.x, a45), m45);
        m67 = fma2(ex1p, add2(vv1.y, a67), m67);
    }

    // merge the 4 edge-slot groups (lane%8 preserved)
    float f[8];
    unpack2(m01, f[0], f[1]); unpack2(m23, f[2], f[3]);
    unpack2(m45, f[4], f[5]); unpack2(m67, f[6], f[7]);
#pragma unroll
    for (int m = 8; m <= 16; m <<= 1) {
#pragma unroll
        for (int i = 0; i < 8; i++) f[i] += __shfl_xor_sync(0xffffffffu, f[i], m);
        d0 += __shfl_xor_sync(0xffffffffu, d0, m);
        d1 += __shfl_xor_sync(0xffffffffu, d1, m);
    }

    if (grp == 0) {
        float i0 = 1.0f / d0, i1 = 1.0f / d1;
        *(float4*)(ap + 4 * l8) =
            make_float4(f[0] * i0, f[1] * i0, f[2] * i0, f[3] * i0);
        *(float4*)(ap + 32 + 4 * l8) =
            make_float4(f[4] * i1, f[5] * i1, f[6] * i1, f[7] * i1);
    }
}

// ---------------- final: out = agg@Wo + bo + x@Wr  (both types via grid.y) ----------------
__global__ void __launch_bounds__(256) final_kernel(
    const float* __restrict__ Wo_a, const float* __restrict__ bo_a,
    const float* __restrict__ x_a,  const float* __restrict__ Wr_a,
    const float* __restrict__ Wo_b, const float* __restrict__ bo_b,
    const float* __restrict__ x_b,  const float* __restrict__ Wr_b,
    float* __restrict__ out)
{
    int type = blockIdx.y;   // 0 = a, 1 = b
    const float* Wo = type ? Wo_b : Wo_a;
    const float* bo = type ? bo_b : bo_a;
    const float* x  = type ? x_b  : x_a;
    const float* Wr = type ? Wr_b : Wr_a;
    const float* agg = type ? g_agg1 : g_agg2;   // a's messages come from relation 2
    float* outp = out + (size_t)type * NN * 32;

    __shared__ float afs[32][65];
    __shared__ float xs[32][65];
    __shared__ __align__(16) float WoS[64][32];
    __shared__ __align__(16) float WrS[64][32];
    __shared__ float boS[32];

    int tid = threadIdx.x;
    int nb  = blockIdx.x * 32;

    if (tid < 32) boS[tid] = bo[tid];

    for (int i = tid; i < 2048; i += 256) {
        int s = i >> 5, o = i & 31;
        WoS[s][o] = Wo[s * 32 + o];
        WrS[s][o] = Wr[s * 32 + o];
        int n2 = nb + (i >> 6), c2 = i & 63;
        afs[i >> 6][c2] = (n2 < NN) ? agg[(size_t)n2 * 64 + c2] : 0.f;
        xs[i >> 6][c2]  = (n2 < NN) ? x[(size_t)n2 * 64 + c2] : 0.f;
    }
    __syncthreads();

    int nl = tid >> 3, p = tid & 7;
    int n = nb + nl;

    u64 o01 = pack2(boS[p * 4 + 0], boS[p * 4 + 1]);
    u64 o23 = pack2(boS[p * 4 + 2], boS[p * 4 + 3]);
#pragma unroll 8
    for (int k = 0; k < 64; k++) {
        float a  = afs[nl][k];
        float xv = xs[nl][k];
        u64 a2 = pack2(a, a);
        u64 x2 = pack2(xv, xv);
        ulonglong2 wo = *(const ulonglong2*)&WoS[k][p * 4];
        ulonglong2 wr = *(const ulonglong2*)&WrS[k][p * 4];
        o01 = fma2(a2, wo.x, o01); o23 = fma2(a2, wo.y, o23);
        o01 = fma2(x2, wr.x, o01); o23 = fma2(x2, wr.y, o23);
    }
    if (n < NN) {
        float o[4];
        unpack2(o01, o[0], o[1]); unpack2(o23, o[2], o[3]);
        float4* op = (float4*)(outp + (size_t)n * 32 + p * 4);
        op[0] = make_float4(o[0], o[1], o[2], o[3]);
    }
}

// ---------------- launch ----------------
extern "C" void kernel_launch(void* const* d_in, const int* in_sizes, int n_in,
                              void* d_out, int out_size)
{
    const float* x_a    = (const float*)d_in[0];
    const float* x_b    = (const float*)d_in[1];
    const float* ea1    = (const float*)d_in[2];
    const float* ea2    = (const float*)d_in[3];
    const float* Wq_a   = (const float*)d_in[4];
    const float* Wk_a   = (const float*)d_in[5];
    const float* Wv_a   = (const float*)d_in[6];
    const float* Wq_b   = (const float*)d_in[7];
    const float* Wk_b   = (const float*)d_in[8];
    const float* Wv_b   = (const float*)d_in[9];
    const float* emb_a  = (const float*)d_in[10];
    const float* emb_b  = (const float*)d_in[11];
    const float* rel1   = (const float*)d_in[12];
    const float* rel2   = (const float*)d_in[13];
    const float* We     = (const float*)d_in[14];
    const float* a_attn = (const float*)d_in[15];
    const float* Wo_a   = (const float*)d_in[16];
    const float* bo_a   = (const float*)d_in[17];
    const float* Wo_b   = (const float*)d_in[18];
    const float* bo_b   = (const float*)d_in[19];
    const float* Wr_a   = (const float*)d_in[20];
    const float* Wr_b   = (const float*)d_in[21];
    const int*   row1   = (const int*)d_in[22];
    const int*   col1   = (const int*)d_in[23];
    const int*   row2   = (const int*)d_in[24];
    const int*   col2   = (const int*)d_in[25];
    float* out = (float*)d_out;

    cudaFuncSetAttribute(prep_kernel, cudaFuncAttributeMaxDynamicSharedMemorySize, PREP_SMEM);

    zero_cnt_kernel<<<(NN + 255) / 256, 256>>>();

    prep_kernel<<<HB + 2 * NB, 512, PREP_SMEM>>>(x_a, Wq_a, Wk_a, Wv_a,
                                                 x_b, Wq_b, Wk_b, Wv_b,
                                                 emb_a, emb_b, rel1, rel2, a_attn,
                                                 col1, col2);

    scan_kernel<<<2, 1024>>>();

    scatter_kernel<<<2048, 256>>>(row1, col1, row2, col2);

    edge_csr_kernel<<<2 * NN / 8, 256>>>(ea1, ea2, We, a_attn);

    dim3 fg((NN + 31) / 32, 2);
    final_kernel<<<fg, 256>>>(Wo_a, bo_a, x_a, Wr_a,
                              Wo_b, bo_b, x_b, Wr_b, out);
}

// round 10
// speedup vs baseline: 1.1482x; 1.1482x over previous
#include <cuda_runtime.h>
#include <cstdint>

#define NN 50000
#define EE 800000
#define ZB 256          // zeroing blocks in prep kernel
#define NB 782          // node blocks per type: ceil(50000/64)
#define EGB 6250        // edge blocks per relation (128 edges/block)

typedef unsigned long long u64;

// ---------------- scratch (device globals; no allocation allowed) ----------------
__device__ __align__(16) float g_sq_a[NN * 2];
__device__ __align__(16) float g_sk_a[NN * 2];
__device__ __align__(16) float g_sq_b[NN * 2];
__device__ __align__(16) float g_sk_b[NN * 2];
__device__ __align__(16) float g_v1[NN * 64];     // v_a + rel1 (natural col order)
__device__ __align__(16) float g_v2[NN * 64];     // v_b + rel2
__device__ __align__(16) float g_agg1[NN * 64];   // Σ ex*(v+rel+eb), dst = b
__device__ __align__(16) float g_agg2[NN * 64];   // dst = a
__device__ __align__(16) float g_den1[NN * 2];    // Σ ex
__device__ __align__(16) float g_den2[NN * 2];

// ---------------- helpers ----------------
__device__ __forceinline__ float tanh_fast(float x) {
    float y;
    asm("tanh.approx.f32 %0, %1;" : "=f"(y) : "f"(x));
    return y;
}
__device__ __forceinline__ u64 pack2(float lo, float hi) {
    u64 r;
    asm("mov.b64 %0, {%1, %2};" : "=l"(r) : "f"(lo), "f"(hi));
    return r;
}
__device__ __forceinline__ void unpack2(u64 v, float& lo, float& hi) {
    asm("mov.b64 {%0, %1}, %2;" : "=f"(lo), "=f"(hi) : "l"(v));
}
__device__ __forceinline__ u64 fma2(u64 a, u64 b, u64 c) {
    u64 d;
    asm("fma.rn.f32x2 %0, %1, %2, %3;" : "=l"(d) : "l"(a), "l"(b), "l"(c));
    return d;
}
__device__ __forceinline__ u64 add2(u64 a, u64 b) {
    u64 d;
    asm("add.rn.f32x2 %0, %1, %2;" : "=l"(d) : "l"(a), "l"(b));
    return d;
}
__device__ __forceinline__ u64 shfl_xor_u64(u64 v, int m) {
    return (u64)__shfl_xor_sync(0xffffffffu, (long long)v, m);
}
__device__ __forceinline__ void red4(float* p, float a, float b, float c, float d) {
    asm volatile("red.global.add.v4.f32 [%0], {%1,%2,%3,%4};"
                 :: "l"(p), "f"(a), "f"(b), "f"(c), "f"(d) : "memory");
}
__device__ __forceinline__ void red2(float* p, float a, float b) {
    asm volatile("red.global.add.v2.f32 [%0], {%1,%2};"
                 :: "l"(p), "f"(a), "f"(b) : "memory");
}

// ---------------- prep: zero scratch + fused-QKV node precompute ----------------
// 512 threads/block, 64 nodes/block; thread tile = 2 nodes x 4 cols x 3 matrices
// dynamic smem: xs[64*65] | Wq[4096] | Wk[4096] | Wv[4096] | emb[64] | rel[64] | a[64]
#define PREP_SMEM ((4160 + 3 * 4096 + 192) * 4)

__global__ void __launch_bounds__(512, 2) prep_kernel(
    const float* __restrict__ x_a, const float* __restrict__ Wq_a,
    const float* __restrict__ Wk_a, const float* __restrict__ Wv_a,
    const float* __restrict__ x_b, const float* __restrict__ Wq_b,
    const float* __restrict__ Wk_b, const float* __restrict__ Wv_b,
    const float* __restrict__ emb_a, const float* __restrict__ emb_b,
    const float* __restrict__ rel1, const float* __restrict__ rel2,
    const float* __restrict__ a_attn)
{
    int b = blockIdx.x;
    int tid = threadIdx.x;

    if (b < ZB) {
        const float4 z = make_float4(0.f, 0.f, 0.f, 0.f);
        int i = b * 512 + tid;
        const int S = ZB * 512;
        for (int k = i; k < NN * 16; k += S) { ((float4*)g_agg1)[k] = z; ((float4*)g_agg2)[k] = z; }
        for (int k = i; k < NN / 2;  k += S) { ((float4*)g_den1)[k] = z; ((float4*)g_den2)[k] = z; }
        return;
    }
    b -= ZB;
    int type = (b >= NB) ? 1 : 0;
    if (type) b -= NB;

    const float* x   = type ? x_b  : x_a;
    const float* Wqg = type ? Wq_b : Wq_a;
    const float* Wkg = type ? Wk_b : Wk_a;
    const float* Wvg = type ? Wv_b : Wv_a;
    const float* emb = type ? emb_b : emb_a;
    const float* rel = type ? rel2 : rel1;
    float* sq   = type ? g_sq_b : g_sq_a;
    float* sk   = type ? g_sk_b : g_sk_a;
    float* vout = type ? g_v2   : g_v1;

    extern __shared__ float sm[];
    float* xs   = sm;              // 64 x 65
    float* Wq   = sm + 4160;
    float* Wk   = Wq + 4096;
    float* Wv   = Wk + 4096;
    float* embS = Wv + 4096;
    float* relS = embS + 64;
    float* aS   = relS + 64;

    int nb = b * 64;

    for (int i = tid; i < 4096; i += 512) {
        int rr = i >> 6, cc = i & 63;
        int n2 = nb + rr;
        xs[rr * 65 + cc] = (n2 < NN) ? __ldg(x + n2 * 64 + cc) : 0.f;
        Wq[i] = __ldg(Wqg + i);
        Wk[i] = __ldg(Wkg + i);
        Wv[i] = __ldg(Wvg + i);
    }
    if (tid < 64) { embS[tid] = emb[tid]; relS[tid] = rel[tid]; aS[tid] = a_attn[tid]; }
    __syncthreads();

    int g = tid >> 4, cg = tid & 15, c0 = cg * 4;   // g: node pair 0..31
    int n0 = nb + g * 2;

    float aq[8], ak[8], av[8];
#pragma unroll
    for (int i = 0; i < 8; i++) { aq[i] = 0.f; ak[i] = 0.f; av[i] = 0.f; }

#pragma unroll 8
    for (int j = 0; j < 64; j++) {
        float4 wq = *(const float4*)&Wq[j * 64 + c0];
        float4 wk = *(const float4*)&Wk[j * 64 + c0];
        float4 wv = *(const float4*)&Wv[j * 64 + c0];
        float x0 = xs[(g * 2 + 0) * 65 + j];
        float x1 = xs[(g * 2 + 1) * 65 + j];
        aq[0] = fmaf(x0, wq.x, aq[0]); aq[1] = fmaf(x0, wq.y, aq[1]);
        aq[2] = fmaf(x0, wq.z, aq[2]); aq[3] = fmaf(x0, wq.w, aq[3]);
        aq[4] = fmaf(x1, wq.x, aq[4]); aq[5] = fmaf(x1, wq.y, aq[5]);
        aq[6] = fmaf(x1, wq.z, aq[6]); aq[7] = fmaf(x1, wq.w, aq[7]);
        ak[0] = fmaf(x0, wk.x, ak[0]); ak[1] = fmaf(x0, wk.y, ak[1]);
        ak[2] = fmaf(x0, wk.z, ak[2]); ak[3] = fmaf(x0, wk.w, ak[3]);
        ak[4] = fmaf(x1, wk.x, ak[4]); ak[5] = fmaf(x1, wk.y, ak[5]);
        ak[6] = fmaf(x1, wk.z, ak[6]); ak[7] = fmaf(x1, wk.w, ak[7]);
        av[0] = fmaf(x0, wv.x, av[0]); av[1] = fmaf(x0, wv.y, av[1]);
        av[2] = fmaf(x0, wv.z, av[2]); av[3] = fmaf(x0, wv.w, av[3]);
        av[4] = fmaf(x1, wv.x, av[4]); av[5] = fmaf(x1, wv.y, av[5]);
        av[6] = fmaf(x1, wv.z, av[6]); av[7] = fmaf(x1, wv.w, av[7]);
    }

    // ---- scores: reduce across the 8 col-groups of each head (16-lane halves) ----
    float pq[2], pk[2];
#pragma unroll
    for (int r = 0; r < 2; r++) {
        float sQ = 0.f, sK = 0.f;
#pragma unroll
        for (int k = 0; k < 4; k++) {
            int c = c0 + k;
            sQ += tanh_fast(aq[r * 4 + k] + embS[c]) * aS[c & 31];
            sK += tanh_fast(ak[r * 4 + k] + embS[c]) * aS[32 + (c & 31)];
        }
        pq[r] = sQ; pk[r] = sK;
    }
#pragma unroll
    for (int m = 1; m < 8; m <<= 1) {
#pragma unroll
        for (int r = 0; r < 2; r++) {
            pq[r] += __shfl_xor_sync(0xffffffffu, pq[r], m);
            pk[r] += __shfl_xor_sync(0xffffffffu, pk[r], m);
        }
    }
    if ((cg & 7) == 0) {
        int h = cg >> 3;
#pragma unroll
        for (int r = 0; r < 2; r++) {
            int n = n0 + r;
            if (n < NN) { sq[n * 2 + h] = pq[r]; sk[n * 2 + h] = pk[r]; }
        }
    }

    // ---- V: store (v + rel) in natural column order ----
#pragma unroll
    for (int r = 0; r < 2; r++) {
        int n = n0 + r;
        if (n < NN) {
            *(float4*)(vout + (size_t)n * 64 + c0) =
                make_float4(av[r*4+0] + relS[c0+0], av[r*4+1] + relS[c0+1],
                            av[r*4+2] + relS[c0+2], av[r*4+3] + relS[c0+3]);
        }
    }
}

// ---------------- merged edge pass: 16 threads/edge, We in registers ----------------
// lane = (eh = lane>>4, jh = (lane>>3)&1, l8 = lane&7).
// Lane holds We[jh*8 .. jh*8+8)[cols {4l8..4l8+3} and {32+4l8..32+4l8+3}] in regs.
// Half-K GEMV per lane; one shfl-xor-8 partner add completes K; jh splits heads
// for the v-load + red4 so REDG lane count stays 16 (+1 red2) per edge.
__global__ void __launch_bounds__(256) edge_kernel(
    const float* __restrict__ ea1, const int* __restrict__ row1, const int* __restrict__ col1,
    const float* __restrict__ ea2, const int* __restrict__ row2, const int* __restrict__ col2,
    const float* __restrict__ We, const float* __restrict__ a_attn)
{
    int bb = blockIdx.x;
    int relid = (bb >= EGB) ? 1 : 0;
    if (relid) bb -= EGB;

    const float* ea  = relid ? ea2  : ea1;
    const int*   row = relid ? row2 : row1;
    const int*   col = relid ? col2 : col1;
    const float* sq  = relid ? g_sq_a : g_sq_b;   // destination-node q scalar
    const float* sk  = relid ? g_sk_b : g_sk_a;   // source-node k scalar
    const float* vsrc = relid ? g_v2 : g_v1;
    float* agg = relid ? g_agg2 : g_agg1;
    float* den = relid ? g_den2 : g_den1;

    int tid  = threadIdx.x;
    int lane = tid & 31;
    int warp = tid >> 5;                    // 0..7
    int eh   = lane >> 4;                   // edge within warp
    int sub  = lane & 15;
    int jh   = sub >> 3;                    // j half: 0 -> j 0..7, 1 -> j 8..15
    int l8   = sub & 7;                     // col group

    // We registers: 8 j x (2 packed pairs per head)
    u64 WR0x[8], WR0y[8], WR1x[8], WR1y[8];
#pragma unroll
    for (int j8 = 0; j8 < 8; j8++) {
        const float4* wp = (const float4*)(We + (jh * 8 + j8) * 64);
        float4 w0 = __ldg(wp + l8);        // cols 4l8..4l8+3
        float4 w1 = __ldg(wp + 8 + l8);    // cols 32+4l8..
        WR0x[j8] = pack2(w0.x, w0.y); WR0y[j8] = pack2(w0.z, w0.w);
        WR1x[j8] = pack2(w1.x, w1.y); WR1y[j8] = pack2(w1.z, w1.w);
    }
    float4 a4 = __ldg((const float4*)(a_attn + 96) + l8);

#pragma unroll 1
    for (int it = 0; it < 8; it++) {
        int e = ((bb * 8 + it) * 8 + warp) * 2 + eh;
        int r = __ldg(row + e), c = __ldg(col + e);

        // this lane's 8 ea values (j half)
        const float4* ea4p = (const float4*)ea + (size_t)e * 4 + jh * 2;
        float4 A = __ldg(ea4p), B = __ldg(ea4p + 1);
        float earr[8] = {A.x, A.y, A.z, A.w, B.x, B.y, B.z, B.w};

        u64 a01 = 0, a23 = 0, a45 = 0, a67 = 0;
#pragma unroll
        for (int j8 = 0; j8 < 8; j8++) {
            u64 ev2 = pack2(earr[j8], earr[j8]);
            a01 = fma2(ev2, WR0x[j8], a01);
            a23 = fma2(ev2, WR0y[j8], a23);
            a45 = fma2(ev2, WR1x[j8], a45);
            a67 = fma2(ev2, WR1y[j8], a67);
        }
        // combine j halves (xor bit3 = jh)
        a01 = add2(a01, shfl_xor_u64(a01, 8));
        a23 = add2(a23, shfl_xor_u64(a23, 8));
        a45 = add2(a45, shfl_xor_u64(a45, 8));
        a67 = add2(a67, shfl_xor_u64(a67, 8));

        float acc[8];
        unpack2(a01, acc[0], acc[1]); unpack2(a23, acc[2], acc[3]);
        unpack2(a45, acc[4], acc[5]); unpack2(a67, acc[6], acc[7]);

        float se0 = tanh_fast(acc[0]) * a4.x + tanh_fast(acc[1]) * a4.y
                  + tanh_fast(acc[2]) * a4.z + tanh_fast(acc[3]) * a4.w;
        float se1 = tanh_fast(acc[4]) * a4.x + tanh_fast(acc[5]) * a4.y
                  + tanh_fast(acc[6]) * a4.z + tanh_fast(acc[7]) * a4.w;
#pragma unroll
        for (int m = 1; m < 8; m <<= 1) {
            se0 += __shfl_xor_sync(0xffffffffu, se0, m);
            se1 += __shfl_xor_sync(0xffffffffu, se1, m);
        }

        float2 sqv = __ldg((const float2*)sq + c);
        float2 skv = __ldg((const float2*)sk + r);
        float ex0 = __expf(sqv.x + skv.x + se0);
        float ex1 = __expf(sqv.y + skv.y + se1);

        if (sub == 0) red2(den + c * 2, ex0, ex1);

        // head split by jh: jh=0 -> head0 (cols 4l8..), jh=1 -> head1 (cols 32+4l8..)
        const float4* vp = (const float4*)(vsrc + (size_t)r * 64) + jh * 8 + l8;
        float4 v = __ldg(vp);
        float w  = jh ? ex1 : ex0;
        float b0 = jh ? acc[4] : acc[0];
        float b1 = jh ? acc[5] : acc[1];
        float b2 = jh ? acc[6] : acc[2];
        float b3 = jh ? acc[7] : acc[3];
        red4(agg + (size_t)c * 64 + jh * 32 + 4 * l8,
             w * (v.x + b0), w * (v.y + b1), w * (v.z + b2), w * (v.w + b3));
    }
}

// ---------------- final: out = (agg/den)@Wo + bo + x@Wr  (both types via grid.y) ----------------
__global__ void __launch_bounds__(256) final_kernel(
    const float* __restrict__ Wo_a, const float* __restrict__ bo_a,
    const float* __restrict__ x_a,  const float* __restrict__ Wr_a,
    const float* __restrict__ Wo_b, const float* __restrict__ bo_b,
    const float* __restrict__ x_b,  const float* __restrict__ Wr_b,
    float* __restrict__ out)
{
    int type = blockIdx.y;   // 0 = a, 1 = b
    const float* Wo = type ? Wo_b : Wo_a;
    const float* bo = type ? bo_b : bo_a;
    const float* x  = type ? x_b  : x_a;
    const float* Wr = type ? Wr_b : Wr_a;
    const float* agg = type ? g_agg1 : g_agg2;   // a's messages come from relation 2
    const float* den = type ? g_den1 : g_den2;
    float* outp = out + (size_t)type * NN * 32;

    __shared__ float afs[32][65];
    __shared__ float xs[32][65];
    __shared__ __align__(16) float WoS[64][32];
    __shared__ __align__(16) float WrS[64][32];
    __shared__ float denS[32][2];
    __shared__ float boS[32];

    int tid = threadIdx.x;
    int nb  = blockIdx.x * 32;

    if (tid < 64) {
        int n2 = nb + (tid >> 1);
        denS[tid >> 1][tid & 1] = (n2 < NN) ? den[n2 * 2 + (tid & 1)] : 0.f;
    }
    if (tid < 32) boS[tid] = bo[tid];
    __syncthreads();

    for (int i = tid; i < 2048; i += 256) {
        int s = i >> 5, o = i & 31;
        WoS[s][o] = Wo[s * 32 + o];
        WrS[s][o] = Wr[s * 32 + o];
        int n2 = nb + (i >> 6), c2 = i & 63;
        float d = denS[i >> 6][c2 >> 5];
        float av = (n2 < NN) ? agg[(size_t)n2 * 64 + c2] : 0.f;
        afs[i >> 6][c2] = (d > 0.f) ? av / d : 0.f;
        xs[i >> 6][c2]  = (n2 < NN) ? x[(size_t)n2 * 64 + c2] : 0.f;
    }
    __syncthreads();

    int nl = tid >> 3, p = tid & 7;
    int n = nb + nl;

    u64 o01 = pack2(boS[p * 4 + 0], boS[p * 4 + 1]);
    u64 o23 = pack2(boS[p * 4 + 2], boS[p * 4 + 3]);
#pragma unroll 8
    for (int k = 0; k < 64; k++) {
        float a  = afs[nl][k];
        float xv = xs[nl][k];
        u64 a2 = pack2(a, a);
        u64 x2 = pack2(xv, xv);
        ulonglong2 wo = *(const ulonglong2*)&WoS[k][p * 4];
        ulonglong2 wr = *(const ulonglong2*)&WrS[k][p * 4];
        o01 = fma2(a2, wo.x, o01); o23 = fma2(a2, wo.y, o23);
        o01 = fma2(x2, wr.x, o01); o23 = fma2(x2, wr.y, o23);
    }
    if (n < NN) {
        float o[4];
        unpack2(o01, o[0], o[1]); unpack2(o23, o[2], o[3]);
        float4* op = (float4*)(outp + (size_t)n * 32 + p * 4);
        op[0] = make_float4(o[0], o[1], o[2], o[3]);
    }
}

// ---------------- launch ----------------
extern "C" void kernel_launch(void* const* d_in, const int* in_sizes, int n_in,
                              void* d_out, int out_size)
{
    const float* x_a    = (const float*)d_in[0];
    const float* x_b    = (const float*)d_in[1];
    const float* ea1    = (const float*)d_in[2];
    const float* ea2    = (const float*)d_in[3];
    const float* Wq_a   = (const float*)d_in[4];
    const float* Wk_a   = (const float*)d_in[5];
    const float* Wv_a   = (const float*)d_in[6];
    const float* Wq_b   = (const float*)d_in[7];
    const float* Wk_b   = (const float*)d_in[8];
    const float* Wv_b   = (const float*)d_in[9];
    const float* emb_a  = (const float*)d_in[10];
    const float* emb_b  = (const float*)d_in[11];
    const float* rel1   = (const float*)d_in[12];
    const float* rel2   = (const float*)d_in[13];
    const float* We     = (const float*)d_in[14];
    const float* a_attn = (const float*)d_in[15];
    const float* Wo_a   = (const float*)d_in[16];
    const float* bo_a   = (const float*)d_in[17];
    const float* Wo_b   = (const float*)d_in[18];
    const float* bo_b   = (const float*)d_in[19];
    const float* Wr_a   = (const float*)d_in[20];
    const float* Wr_b   = (const float*)d_in[21];
    const int*   row1   = (const int*)d_in[22];
    const int*   col1   = (const int*)d_in[23];
    const int*   row2   = (const int*)d_in[24];
    const int*   col2   = (const int*)d_in[25];
    float* out = (float*)d_out;

    cudaFuncSetAttribute(prep_kernel, cudaFuncAttributeMaxDynamicSharedMemorySize, PREP_SMEM);

    prep_kernel<<<ZB + 2 * NB, 512, PREP_SMEM>>>(x_a, Wq_a, Wk_a, Wv_a,
                                                 x_b, Wq_b, Wk_b, Wv_b,
                                                 emb_a, emb_b, rel1, rel2, a_attn);

    edge_kernel<<<2 * EGB, 256>>>(ea1, row1, col1, ea2, row2, col2, We, a_attn);

    dim3 fg((NN + 31) / 32, 2);
    final_kernel<<<fg, 256>>>(Wo_a, bo_a, x_a, Wr_a,
                              Wo_b, bo_b, x_b, Wr_b, out);
}

// round 12
// speedup vs baseline: 1.3272x; 1.1559x over previous
#include <cuda_runtime.h>
#include <cstdint>

#define NN 50000
#define EE 800000
#define ZB 256          // zeroing blocks in prep kernel
#define NB 782          // node blocks per type: ceil(50000/64)
#define EGB 6250        // edge blocks per relation (128 edges/block)

typedef unsigned long long u64;

// ---------------- scratch (device globals; no allocation allowed) ----------------
__device__ __align__(16) float g_sq_a[NN * 2];
__device__ __align__(16) float g_sk_a[NN * 2];
__device__ __align__(16) float g_sq_b[NN * 2];
__device__ __align__(16) float g_sk_b[NN * 2];
__device__ __align__(16) float g_v1[NN * 64];     // v_a + rel1 (natural col order)
__device__ __align__(16) float g_v2[NN * 64];     // v_b + rel2
__device__ __align__(16) float g_agg1[NN * 64];   // Σ ex*(v+rel+eb), dst = b
__device__ __align__(16) float g_agg2[NN * 64];   // dst = a
__device__ __align__(16) float g_den1[NN * 2];    // Σ ex
__device__ __align__(16) float g_den2[NN * 2];

// ---------------- helpers ----------------
__device__ __forceinline__ float tanh_fast(float x) {
    float y;
    asm("tanh.approx.f32 %0, %1;" : "=f"(y) : "f"(x));
    return y;
}
__device__ __forceinline__ u64 pack2(float lo, float hi) {
    u64 r;
    asm("mov.b64 %0, {%1, %2};" : "=l"(r) : "f"(lo), "f"(hi));
    return r;
}
__device__ __forceinline__ void unpack2(u64 v, float& lo, float& hi) {
    asm("mov.b64 {%0, %1}, %2;" : "=f"(lo), "=f"(hi) : "l"(v));
}
__device__ __forceinline__ u64 fma2(u64 a, u64 b, u64 c) {
    u64 d;
    asm("fma.rn.f32x2 %0, %1, %2, %3;" : "=l"(d) : "l"(a), "l"(b), "l"(c));
    return d;
}
__device__ __forceinline__ void red4(float* p, float a, float b, float c, float d) {
    asm volatile("red.global.add.v4.f32 [%0], {%1,%2,%3,%4};"
                 :: "l"(p), "f"(a), "f"(b), "f"(c), "f"(d) : "memory");
}
__device__ __forceinline__ void red2(float* p, float a, float b) {
    asm volatile("red.global.add.v2.f32 [%0], {%1,%2};"
                 :: "l"(p), "f"(a), "f"(b) : "memory");
}

// ---------------- prep: zero scratch + fused-QKV node precompute ----------------
// 256 threads/block, 64 nodes/block; thread tile = 4 nodes x 4 cols x 3 matrices
// dynamic smem: xs[64*65] | Wq[4096] | Wk[4096] | Wv[4096] | emb[64] | rel[64] | a[64]
#define PREP_SMEM ((4160 + 3 * 4096 + 192) * 4)

__global__ void __launch_bounds__(256, 2) prep_kernel(
    const float* __restrict__ x_a, const float* __restrict__ Wq_a,
    const float* __restrict__ Wk_a, const float* __restrict__ Wv_a,
    const float* __restrict__ x_b, const float* __restrict__ Wq_b,
    const float* __restrict__ Wk_b, const float* __restrict__ Wv_b,
    const float* __restrict__ emb_a, const float* __restrict__ emb_b,
    const float* __restrict__ rel1, const float* __restrict__ rel2,
    const float* __restrict__ a_attn)
{
    int b = blockIdx.x;
    int tid = threadIdx.x;

    if (b < ZB) {
        const float4 z = make_float4(0.f, 0.f, 0.f, 0.f);
        int i = b * 256 + tid;
        const int S = ZB * 256;
        for (int k = i; k < NN * 16; k += S) { ((float4*)g_agg1)[k] = z; ((float4*)g_agg2)[k] = z; }
        for (int k = i; k < NN / 2;  k += S) { ((float4*)g_den1)[k] = z; ((float4*)g_den2)[k] = z; }
        return;
    }
    b -= ZB;
    int type = (b >= NB) ? 1 : 0;
    if (type) b -= NB;

    const float* x   = type ? x_b  : x_a;
    const float* Wqg = type ? Wq_b : Wq_a;
    const float* Wkg = type ? Wk_b : Wk_a;
    const float* Wvg = type ? Wv_b : Wv_a;
    const float* emb = type ? emb_b : emb_a;
    const float* rel = type ? rel2 : rel1;
    float* sq   = type ? g_sq_b : g_sq_a;
    float* sk   = type ? g_sk_b : g_sk_a;
    float* vout = type ? g_v2   : g_v1;

    extern __shared__ float sm[];
    float* xs   = sm;              // 64 x 65
    float* Wq   = sm + 4160;
    float* Wk   = Wq + 4096;
    float* Wv   = Wk + 4096;
    float* embS = Wv + 4096;
    float* relS = embS + 64;
    float* aS   = relS + 64;

    int nb = b * 64;

    for (int i = tid; i < 4096; i += 256) {
        int rr = i >> 6, cc = i & 63;
        int n2 = nb + rr;
        xs[rr * 65 + cc] = (n2 < NN) ? __ldg(x + n2 * 64 + cc) : 0.f;
        Wq[i] = __ldg(Wqg + i);
        Wk[i] = __ldg(Wkg + i);
        Wv[i] = __ldg(Wvg + i);
    }
    if (tid < 64) { embS[tid] = emb[tid]; relS[tid] = rel[tid]; aS[tid] = a_attn[tid]; }
    __syncthreads();

    int g = tid >> 4, cg = tid & 15, c0 = cg * 4;   // g: node quad 0..15
    int n0 = nb + g * 4;

    float aq[16], ak[16], av[16];
#pragma unroll
    for (int i = 0; i < 16; i++) { aq[i] = 0.f; ak[i] = 0.f; av[i] = 0.f; }

#pragma unroll 4
    for (int j = 0; j < 64; j++) {
        float4 wq = *(const float4*)&Wq[j * 64 + c0];
        float4 wk = *(const float4*)&Wk[j * 64 + c0];
        float4 wv = *(const float4*)&Wv[j * 64 + c0];
#pragma unroll
        for (int r = 0; r < 4; r++) {
            float xv = xs[(g * 4 + r) * 65 + j];
            aq[r*4+0] = fmaf(xv, wq.x, aq[r*4+0]);
            aq[r*4+1] = fmaf(xv, wq.y, aq[r*4+1]);
            aq[r*4+2] = fmaf(xv, wq.z, aq[r*4+2]);
            aq[r*4+3] = fmaf(xv, wq.w, aq[r*4+3]);
            ak[r*4+0] = fmaf(xv, wk.x, ak[r*4+0]);
            ak[r*4+1] = fmaf(xv, wk.y, ak[r*4+1]);
            ak[r*4+2] = fmaf(xv, wk.z, ak[r*4+2]);
            ak[r*4+3] = fmaf(xv, wk.w, ak[r*4+3]);
            av[r*4+0] = fmaf(xv, wv.x, av[r*4+0]);
            av[r*4+1] = fmaf(xv, wv.y, av[r*4+1]);
            av[r*4+2] = fmaf(xv, wv.z, av[r*4+2]);
            av[r*4+3] = fmaf(xv, wv.w, av[r*4+3]);
        }
    }

    // ---- scores: reduce across the 8 col-groups of each head ----
    float pq[4], pk[4];
#pragma unroll
    for (int r = 0; r < 4; r++) {
        float sQ = 0.f, sK = 0.f;
#pragma unroll
        for (int k = 0; k < 4; k++) {
            int c = c0 + k;
            sQ += tanh_fast(aq[r * 4 + k] + embS[c]) * aS[c & 31];
            sK += tanh_fast(ak[r * 4 + k] + embS[c]) * aS[32 + (c & 31)];
        }
        pq[r] = sQ; pk[r] = sK;
    }
#pragma unroll
    for (int m = 1; m < 8; m <<= 1) {
#pragma unroll
        for (int r = 0; r < 4; r++) {
            pq[r] += __shfl_xor_sync(0xffffffffu, pq[r], m);
            pk[r] += __shfl_xor_sync(0xffffffffu, pk[r], m);
        }
    }
    if ((cg & 7) == 0) {
        int h = cg >> 3;
#pragma unroll
        for (int r = 0; r < 4; r++) {
            int n = n0 + r;
            if (n < NN) { sq[n * 2 + h] = pq[r]; sk[n * 2 + h] = pk[r]; }
        }
    }

    // ---- V: store (v + rel) in natural column order ----
#pragma unroll
    for (int r = 0; r < 4; r++) {
        int n = n0 + r;
        if (n < NN) {
            *(float4*)(vout + (size_t)n * 64 + c0) =
                make_float4(av[r*4+0] + relS[c0+0], av[r*4+1] + relS[c0+1],
                            av[r*4+2] + relS[c0+2], av[r*4+3] + relS[c0+3]);
        }
    }
}

// ---------------- merged edge pass: 8 threads/edge (round-6 measured-best) ----------------
// lane l owns cols {4l..4l+3} (head 0) and {32+4l..32+4l+3} (head 1):
// We reads are two conflict-free LDS.128 per j; v/agg natural + contiguous.
__global__ void __launch_bounds__(256) edge_kernel(
    const float* __restrict__ ea1, const int* __restrict__ row1, const int* __restrict__ col1,
    const float* __restrict__ ea2, const int* __restrict__ row2, const int* __restrict__ col2,
    const float* __restrict__ We, const float* __restrict__ a_attn)
{
    int bb = blockIdx.x;
    int relid = (bb >= EGB) ? 1 : 0;
    if (relid) bb -= EGB;

    const float* ea  = relid ? ea2  : ea1;
    const int*   row = relid ? row2 : row1;
    const int*   col = relid ? col2 : col1;
    const float* sq  = relid ? g_sq_a : g_sq_b;   // destination-node q scalar
    const float* sk  = relid ? g_sk_b : g_sk_a;   // source-node k scalar
    const float* vsrc = relid ? g_v2 : g_v1;
    float* agg = relid ? g_agg2 : g_agg1;
    float* den = relid ? g_den2 : g_den1;

    __shared__ __align__(16) float WeS[1024];     // [16][64] natural
    __shared__ float a4S[32];
    int tid = threadIdx.x;
    for (int i = tid; i < 1024; i += 256) WeS[i] = We[i];
    if (tid < 32) a4S[tid] = a_attn[96 + tid];
    __syncthreads();

    int lane = tid & 7;
    int grp  = tid >> 3;
    const float4* WeV = (const float4*)WeS;       // row j = 16 float4s

#pragma unroll 1
    for (int it = 0; it < 4; it++) {
        int e = (bb * 4 + it) * 32 + grp;
        int r = __ldg(row + e), c = __ldg(col + e);

        const float4* ea4p = (const float4*)ea + (size_t)e * 4;
        float4 A = __ldg(ea4p), B = __ldg(ea4p + 1), C = __ldg(ea4p + 2), D = __ldg(ea4p + 3);
        float ear[16] = {A.x, A.y, A.z, A.w, B.x, B.y, B.z, B.w,
                         C.x, C.y, C.z, C.w, D.x, D.y, D.z, D.w};

        float acc[8];
#pragma unroll
        for (int i = 0; i < 8; i++) acc[i] = 0.f;
#pragma unroll
        for (int j = 0; j < 16; j++) {
            float ev = ear[j];
            float4 w0 = WeV[j * 16 + lane];        // cols 4l..4l+3
            float4 w1 = WeV[j * 16 + 8 + lane];    // cols 32+4l..32+4l+3
            acc[0] = fmaf(ev, w0.x, acc[0]); acc[1] = fmaf(ev, w0.y, acc[1]);
            acc[2] = fmaf(ev, w0.z, acc[2]); acc[3] = fmaf(ev, w0.w, acc[3]);
            acc[4] = fmaf(ev, w1.x, acc[4]); acc[5] = fmaf(ev, w1.y, acc[5]);
            acc[6] = fmaf(ev, w1.z, acc[6]); acc[7] = fmaf(ev, w1.w, acc[7]);
        }

        // score: head0 cols 4l+t (a idx 4l+t), head1 cols 32+4l+t (a idx 4l+t)
        float se0 = 0.f, se1 = 0.f;
#pragma unroll
        for (int t = 0; t < 4; t++) {
            float av = a4S[4 * lane + t];
            se0 += tanh_fast(acc[t])     * av;
            se1 += tanh_fast(acc[4 + t]) * av;
        }
#pragma unroll
        for (int m = 1; m < 8; m <<= 1) {
            se0 += __shfl_xor_sync(0xffffffffu, se0, m);
            se1 += __shfl_xor_sync(0xffffffffu, se1, m);
        }

        float2 sqv = __ldg((const float2*)sq + c);
        float2 skv = __ldg((const float2*)sk + r);
        float ex0 = __expf(sqv.x + skv.x + se0);
        float ex1 = __expf(sqv.y + skv.y + se1);

        if (lane == 0) red2(den + c * 2, ex0, ex1);

        // v gather: natural layout, contiguous per 8-lane group
        const float4* vp = (const float4*)vsrc + (size_t)r * 16;
        float4 v0 = __ldg(vp + lane);              // cols 4l..4l+3
        float4 v1 = __ldg(vp + 8 + lane);          // cols 32+4l..

        float* ap = agg + (size_t)c * 64;
        red4(ap + 4 * lane,
             ex0 * (v0.x + acc[0]), ex0 * (v0.y + acc[1]),
             ex0 * (v0.z + acc[2]), ex0 * (v0.w + acc[3]));
        red4(ap + 32 + 4 * lane,
             ex1 * (v1.x + acc[4]), ex1 * (v1.y + acc[5]),
             ex1 * (v1.z + acc[6]), ex1 * (v1.w + acc[7]));
    }
}

// ---------------- final: out = (agg/den)@Wo + bo + x@Wr  (both types via grid.y) ----------------
__global__ void __launch_bounds__(256) final_kernel(
    const float* __restrict__ Wo_a, const float* __restrict__ bo_a,
    const float* __restrict__ x_a,  const float* __restrict__ Wr_a,
    const float* __restrict__ Wo_b, const float* __restrict__ bo_b,
    const float* __restrict__ x_b,  const float* __restrict__ Wr_b,
    float* __restrict__ out)
{
    int type = blockIdx.y;   // 0 = a, 1 = b
    const float* Wo = type ? Wo_b : Wo_a;
    const float* bo = type ? bo_b : bo_a;
    const float* x  = type ? x_b  : x_a;
    const float* Wr = type ? Wr_b : Wr_a;
    const float* agg = type ? g_agg1 : g_agg2;   // a's messages come from relation 2
    const float* den = type ? g_den1 : g_den2;
    float* outp = out + (size_t)type * NN * 32;

    __shared__ float afs[32][65];
    __shared__ float xs[32][65];
    __shared__ __align__(16) float WoS[64][32];
    __shared__ __align__(16) float WrS[64][32];
    __shared__ float denS[32][2];
    __shared__ float boS[32];

    int tid = threadIdx.x;
    int nb  = blockIdx.x * 32;

    if (tid < 64) {
        int n2 = nb + (tid >> 1);
        denS[tid >> 1][tid & 1] = (n2 < NN) ? den[n2 * 2 + (tid & 1)] : 0.f;
    }
    if (tid < 32) boS[tid] = bo[tid];
    __syncthreads();

    for (int i = tid; i < 2048; i += 256) {
        int s = i >> 5, o = i & 31;
        WoS[s][o] = Wo[s * 32 + o];
        WrS[s][o] = Wr[s * 32 + o];
        int n2 = nb + (i >> 6), c2 = i & 63;
        float d = denS[i >> 6][c2 >> 5];
        float av = (n2 < NN) ? agg[(size_t)n2 * 64 + c2] : 0.f;
        afs[i >> 6][c2] = (d > 0.f) ? av / d : 0.f;
        xs[i >> 6][c2]  = (n2 < NN) ? x[(size_t)n2 * 64 + c2] : 0.f;
    }
    __syncthreads();

    int nl = tid >> 3, p = tid & 7;
    int n = nb + nl;

    u64 o01 = pack2(boS[p * 4 + 0], boS[p * 4 + 1]);
    u64 o23 = pack2(boS[p * 4 + 2], boS[p * 4 + 3]);
#pragma unroll 8
    for (int k = 0; k < 64; k++) {
        float a  = afs[nl][k];
        float xv = xs[nl][k];
        u64 a2 = pack2(a, a);
        u64 x2 = pack2(xv, xv);
        ulonglong2 wo = *(const ulonglong2*)&WoS[k][p * 4];
        ulonglong2 wr = *(const ulonglong2*)&WrS[k][p * 4];
        o01 = fma2(a2, wo.x, o01); o23 = fma2(a2, wo.y, o23);
        o01 = fma2(x2, wr.x, o01); o23 = fma2(x2, wr.y, o23);
    }
    if (n < NN) {
        float o[4];
        unpack2(o01, o[0], o[1]); unpack2(o23, o[2], o[3]);
        float4* op = (float4*)(outp + (size_t)n * 32 + p * 4);
        op[0] = make_float4(o[0], o[1], o[2], o[3]);
    }
}

// ---------------- launch ----------------
extern "C" void kernel_launch(void* const* d_in, const int* in_sizes, int n_in,
                              void* d_out, int out_size)
{
    const float* x_a    = (const float*)d_in[0];
    const float* x_b    = (const float*)d_in[1];
    const float* ea1    = (const float*)d_in[2];
    const float* ea2    = (const float*)d_in[3];
    const float* Wq_a   = (const float*)d_in[4];
    const float* Wk_a   = (const float*)d_in[5];
    const float* Wv_a   = (const float*)d_in[6];
    const float* Wq_b   = (const float*)d_in[7];
    const float* Wk_b   = (const float*)d_in[8];
    const float* Wv_b   = (const float*)d_in[9];
    const float* emb_a  = (const float*)d_in[10];
    const float* emb_b  = (const float*)d_in[11];
    const float* rel1   = (const float*)d_in[12];
    const float* rel2   = (const float*)d_in[13];
    const float* We     = (const float*)d_in[14];
    const float* a_attn = (const float*)d_in[15];
    const float* Wo_a   = (const float*)d_in[16];
    const float* bo_a   = (const float*)d_in[17];
    const float* Wo_b   = (const float*)d_in[18];
    const float* bo_b   = (const float*)d_in[19];
    const float* Wr_a   = (const float*)d_in[20];
    const float* Wr_b   = (const float*)d_in[21];
    const int*   row1   = (const int*)d_in[22];
    const int*   col1   = (const int*)d_in[23];
    const int*   row2   = (const int*)d_in[24];
    const int*   col2   = (const int*)d_in[25];
    float* out = (float*)d_out;

    cudaFuncSetAttribute(prep_kernel, cudaFuncAttributeMaxDynamicSharedMemorySize, PREP_SMEM);

    prep_kernel<<<ZB + 2 * NB, 256, PREP_SMEM>>>(x_a, Wq_a, Wk_a, Wv_a,
                                                 x_b, Wq_b, Wk_b, Wv_b,
                                                 emb_a, emb_b, rel1, rel2, a_attn);

    edge_kernel<<<2 * EGB, 256>>>(ea1, row1, col1, ea2, row2, col2, We, a_attn);

    dim3 fg((NN + 31) / 32, 2);
    final_kernel<<<fg, 256>>>(Wo_a, bo_a, x_a, Wr_a,
                              Wo_b, bo_b, x_b, Wr_b, out);
}

// round 13
// speedup vs baseline: 1.3755x; 1.0364x over previous
#include <cuda_runtime.h>
#include <cstdint>

#define NN 50000
#define EE 800000
#define ZB 256          // zeroing blocks in prep kernel
#define NB 782          // node blocks per type: ceil(50000/64)
#define EGB 6250        // edge blocks per relation (128 edges/block)

typedef unsigned long long u64;

// ---------------- scratch (device globals; no allocation allowed) ----------------
__device__ __align__(16) float g_sq_a[NN * 2];
__device__ __align__(16) float g_sk_a[NN * 2];
__device__ __align__(16) float g_sq_b[NN * 2];
__device__ __align__(16) float g_sk_b[NN * 2];
__device__ __align__(16) float g_v1[NN * 64];     // v_a + rel1 (natural col order)
__device__ __align__(16) float g_v2[NN * 64];     // v_b + rel2
__device__ __align__(16) float g_agg1[NN * 64];   // Σ ex*(v+rel+eb), dst = b
__device__ __align__(16) float g_agg2[NN * 64];   // dst = a
__device__ __align__(16) float g_den1[NN * 2];    // Σ ex
__device__ __align__(16) float g_den2[NN * 2];

// ---------------- helpers ----------------
__device__ __forceinline__ float tanh_fast(float x) {
    float y;
    asm("tanh.approx.f32 %0, %1;" : "=f"(y) : "f"(x));
    return y;
}
__device__ __forceinline__ u64 pack2(float lo, float hi) {
    u64 r;
    asm("mov.b64 %0, {%1, %2};" : "=l"(r) : "f"(lo), "f"(hi));
    return r;
}
__device__ __forceinline__ void unpack2(u64 v, float& lo, float& hi) {
    asm("mov.b64 {%0, %1}, %2;" : "=f"(lo), "=f"(hi) : "l"(v));
}
__device__ __forceinline__ u64 fma2(u64 a, u64 b, u64 c) {
    u64 d;
    asm("fma.rn.f32x2 %0, %1, %2, %3;" : "=l"(d) : "l"(a), "l"(b), "l"(c));
    return d;
}
__device__ __forceinline__ void red4(float* p, float a, float b, float c, float d) {
    asm volatile("red.global.add.v4.f32 [%0], {%1,%2,%3,%4};"
                 :: "l"(p), "f"(a), "f"(b), "f"(c), "f"(d) : "memory");
}
__device__ __forceinline__ void red2(float* p, float a, float b) {
    asm volatile("red.global.add.v2.f32 [%0], {%1,%2};"
                 :: "l"(p), "f"(a), "f"(b) : "memory");
}

// ---------------- prep: zero scratch + fused-QKV node precompute ----------------
// 256 threads/block, 64 nodes/block; thread tile = 4 nodes x 4 cols x 3 matrices,
// f32x2-packed inner loop; __launch_bounds__(256,3) for 3 blocks/SM.
// dynamic smem: xs[64*65] | Wq[4096] | Wk[4096] | Wv[4096] | emb[64] | rel[64] | a[64]
#define PREP_SMEM ((4160 + 3 * 4096 + 192) * 4)

__global__ void __launch_bounds__(256, 3) prep_kernel(
    const float* __restrict__ x_a, const float* __restrict__ Wq_a,
    const float* __restrict__ Wk_a, const float* __restrict__ Wv_a,
    const float* __restrict__ x_b, const float* __restrict__ Wq_b,
    const float* __restrict__ Wk_b, const float* __restrict__ Wv_b,
    const float* __restrict__ emb_a, const float* __restrict__ emb_b,
    const float* __restrict__ rel1, const float* __restrict__ rel2,
    const float* __restrict__ a_attn)
{
    int b = blockIdx.x;
    int tid = threadIdx.x;

    if (b < ZB) {
        const float4 z = make_float4(0.f, 0.f, 0.f, 0.f);
        int i = b * 256 + tid;
        const int S = ZB * 256;
        for (int k = i; k < NN * 16; k += S) { ((float4*)g_agg1)[k] = z; ((float4*)g_agg2)[k] = z; }
        for (int k = i; k < NN / 2;  k += S) { ((float4*)g_den1)[k] = z; ((float4*)g_den2)[k] = z; }
        return;
    }
    b -= ZB;
    int type = (b >= NB) ? 1 : 0;
    if (type) b -= NB;

    const float* x   = type ? x_b  : x_a;
    const float* Wqg = type ? Wq_b : Wq_a;
    const float* Wkg = type ? Wk_b : Wk_a;
    const float* Wvg = type ? Wv_b : Wv_a;
    const float* emb = type ? emb_b : emb_a;
    const float* rel = type ? rel2 : rel1;
    float* sq   = type ? g_sq_b : g_sq_a;
    float* sk   = type ? g_sk_b : g_sk_a;
    float* vout = type ? g_v2   : g_v1;

    extern __shared__ float sm[];
    float* xs   = sm;              // 64 x 65
    float* Wq   = sm + 4160;
    float* Wk   = Wq + 4096;
    float* Wv   = Wk + 4096;
    float* embS = Wv + 4096;
    float* relS = embS + 64;
    float* aS   = relS + 64;

    int nb = b * 64;

    for (int i = tid; i < 4096; i += 256) {
        int rr = i >> 6, cc = i & 63;
        int n2 = nb + rr;
        xs[rr * 65 + cc] = (n2 < NN) ? __ldg(x + n2 * 64 + cc) : 0.f;
        Wq[i] = __ldg(Wqg + i);
        Wk[i] = __ldg(Wkg + i);
        Wv[i] = __ldg(Wvg + i);
    }
    if (tid < 64) { embS[tid] = emb[tid]; relS[tid] = rel[tid]; aS[tid] = a_attn[tid]; }
    __syncthreads();

    int g = tid >> 4, cg = tid & 15, c0 = cg * 4;   // g: node quad 0..15
    int n0 = nb + g * 4;

    const ulonglong2* WqV = (const ulonglong2*)Wq;  // row j = 16 ulonglong2
    const ulonglong2* WkV = (const ulonglong2*)Wk;
    const ulonglong2* WvV = (const ulonglong2*)Wv;

    // packed accumulators: [node r][pair p] for each of Q/K/V; 24 u64 total
    u64 Aq[8], Ak[8], Av[8];
#pragma unroll
    for (int i = 0; i < 8; i++) { Aq[i] = 0; Ak[i] = 0; Av[i] = 0; }

#pragma unroll 4
    for (int j = 0; j < 64; j++) {
        ulonglong2 wq = WqV[j * 16 + cg];
        ulonglong2 wk = WkV[j * 16 + cg];
        ulonglong2 wv = WvV[j * 16 + cg];
#pragma unroll
        for (int r = 0; r < 4; r++) {
            float xv = xs[(g * 4 + r) * 65 + j];
            u64 x2 = pack2(xv, xv);
            Aq[r * 2 + 0] = fma2(x2, wq.x, Aq[r * 2 + 0]);
            Aq[r * 2 + 1] = fma2(x2, wq.y, Aq[r * 2 + 1]);
            Ak[r * 2 + 0] = fma2(x2, wk.x, Ak[r * 2 + 0]);
            Ak[r * 2 + 1] = fma2(x2, wk.y, Ak[r * 2 + 1]);
            Av[r * 2 + 0] = fma2(x2, wv.x, Av[r * 2 + 0]);
            Av[r * 2 + 1] = fma2(x2, wv.y, Av[r * 2 + 1]);
        }
    }

    float aq[16], ak[16], av[16];
#pragma unroll
    for (int r = 0; r < 4; r++) {
        unpack2(Aq[r * 2 + 0], aq[r * 4 + 0], aq[r * 4 + 1]);
        unpack2(Aq[r * 2 + 1], aq[r * 4 + 2], aq[r * 4 + 3]);
        unpack2(Ak[r * 2 + 0], ak[r * 4 + 0], ak[r * 4 + 1]);
        unpack2(Ak[r * 2 + 1], ak[r * 4 + 2], ak[r * 4 + 3]);
        unpack2(Av[r * 2 + 0], av[r * 4 + 0], av[r * 4 + 1]);
        unpack2(Av[r * 2 + 1], av[r * 4 + 2], av[r * 4 + 3]);
    }

    // ---- scores: reduce across the 8 col-groups of each head ----
    float pq[4], pk[4];
#pragma unroll
    for (int r = 0; r < 4; r++) {
        float sQ = 0.f, sK = 0.f;
#pragma unroll
        for (int k = 0; k < 4; k++) {
            int c = c0 + k;
            sQ += tanh_fast(aq[r * 4 + k] + embS[c]) * aS[c & 31];
            sK += tanh_fast(ak[r * 4 + k] + embS[c]) * aS[32 + (c & 31)];
        }
        pq[r] = sQ; pk[r] = sK;
    }
#pragma unroll
    for (int m = 1; m < 8; m <<= 1) {
#pragma unroll
        for (int r = 0; r < 4; r++) {
            pq[r] += __shfl_xor_sync(0xffffffffu, pq[r], m);
            pk[r] += __shfl_xor_sync(0xffffffffu, pk[r], m);
        }
    }
    if ((cg & 7) == 0) {
        int h = cg >> 3;
#pragma unroll
        for (int r = 0; r < 4; r++) {
            int n = n0 + r;
            if (n < NN) { sq[n * 2 + h] = pq[r]; sk[n * 2 + h] = pk[r]; }
        }
    }

    // ---- V: store (v + rel) in natural column order ----
#pragma unroll
    for (int r = 0; r < 4; r++) {
        int n = n0 + r;
        if (n < NN) {
            *(float4*)(vout + (size_t)n * 64 + c0) =
                make_float4(av[r*4+0] + relS[c0+0], av[r*4+1] + relS[c0+1],
                            av[r*4+2] + relS[c0+2], av[r*4+3] + relS[c0+3]);
        }
    }
}

// ---------------- merged edge pass: 8 threads/edge (round-6 measured-best) ----------------
// lane l owns cols {4l..4l+3} (head 0) and {32+4l..32+4l+3} (head 1):
// We reads are two conflict-free LDS.128 per j; v/agg natural + contiguous.
__global__ void __launch_bounds__(256) edge_kernel(
    const float* __restrict__ ea1, const int* __restrict__ row1, const int* __restrict__ col1,
    const float* __restrict__ ea2, const int* __restrict__ row2, const int* __restrict__ col2,
    const float* __restrict__ We, const float* __restrict__ a_attn)
{
    int bb = blockIdx.x;
    int relid = (bb >= EGB) ? 1 : 0;
    if (relid) bb -= EGB;

    const float* ea  = relid ? ea2  : ea1;
    const int*   row = relid ? row2 : row1;
    const int*   col = relid ? col2 : col1;
    const float* sq  = relid ? g_sq_a : g_sq_b;   // destination-node q scalar
    const float* sk  = relid ? g_sk_b : g_sk_a;   // source-node k scalar
    const float* vsrc = relid ? g_v2 : g_v1;
    float* agg = relid ? g_agg2 : g_agg1;
    float* den = relid ? g_den2 : g_den1;

    __shared__ __align__(16) float WeS[1024];     // [16][64] natural
    __shared__ float a4S[32];
    int tid = threadIdx.x;
    for (int i = tid; i < 1024; i += 256) WeS[i] = We[i];
    if (tid < 32) a4S[tid] = a_attn[96 + tid];
    __syncthreads();

    int lane = tid & 7;
    int grp  = tid >> 3;
    const float4* WeV = (const float4*)WeS;       // row j = 16 float4s

#pragma unroll 1
    for (int it = 0; it < 4; it++) {
        int e = (bb * 4 + it) * 32 + grp;
        int r = __ldg(row + e), c = __ldg(col + e);

        const float4* ea4p = (const float4*)ea + (size_t)e * 4;
        float4 A = __ldg(ea4p), B = __ldg(ea4p + 1), C = __ldg(ea4p + 2), D = __ldg(ea4p + 3);
        float ear[16] = {A.x, A.y, A.z, A.w, B.x, B.y, B.z, B.w,
                         C.x, C.y, C.z, C.w, D.x, D.y, D.z, D.w};

        float acc[8];
#pragma unroll
        for (int i = 0; i < 8; i++) acc[i] = 0.f;
#pragma unroll
        for (int j = 0; j < 16; j++) {
            float ev = ear[j];
            float4 w0 = WeV[j * 16 + lane];        // cols 4l..4l+3
            float4 w1 = WeV[j * 16 + 8 + lane];    // cols 32+4l..32+4l+3
            acc[0] = fmaf(ev, w0.x, acc[0]); acc[1] = fmaf(ev, w0.y, acc[1]);
            acc[2] = fmaf(ev, w0.z, acc[2]); acc[3] = fmaf(ev, w0.w, acc[3]);
            acc[4] = fmaf(ev, w1.x, acc[4]); acc[5] = fmaf(ev, w1.y, acc[5]);
            acc[6] = fmaf(ev, w1.z, acc[6]); acc[7] = fmaf(ev, w1.w, acc[7]);
        }

        // score: head0 cols 4l+t (a idx 4l+t), head1 cols 32+4l+t (a idx 4l+t)
        float se0 = 0.f, se1 = 0.f;
#pragma unroll
        for (int t = 0; t < 4; t++) {
            float av = a4S[4 * lane + t];
            se0 += tanh_fast(acc[t])     * av;
            se1 += tanh_fast(acc[4 + t]) * av;
        }
#pragma unroll
        for (int m = 1; m < 8; m <<= 1) {
            se0 += __shfl_xor_sync(0xffffffffu, se0, m);
            se1 += __shfl_xor_sync(0xffffffffu, se1, m);
        }

        float2 sqv = __ldg((const float2*)sq + c);
        float2 skv = __ldg((const float2*)sk + r);
        float ex0 = __expf(sqv.x + skv.x + se0);
        float ex1 = __expf(sqv.y + skv.y + se1);

        if (lane == 0) red2(den + c * 2, ex0, ex1);

        // v gather: natural layout, contiguous per 8-lane group
        const float4* vp = (const float4*)vsrc + (size_t)r * 16;
        float4 v0 = __ldg(vp + lane);              // cols 4l..4l+3
        float4 v1 = __ldg(vp + 8 + lane);          // cols 32+4l..

        float* ap = agg + (size_t)c * 64;
        red4(ap + 4 * lane,
             ex0 * (v0.x + acc[0]), ex0 * (v0.y + acc[1]),
             ex0 * (v0.z + acc[2]), ex0 * (v0.w + acc[3]));
        red4(ap + 32 + 4 * lane,
             ex1 * (v1.x + acc[4]), ex1 * (v1.y + acc[5]),
             ex1 * (v1.z + acc[6]), ex1 * (v1.w + acc[7]));
    }
}

// ---------------- final: out = (agg/den)@Wo + bo + x@Wr  (both types via grid.y) ----------------
__global__ void __launch_bounds__(256) final_kernel(
    const float* __restrict__ Wo_a, const float* __restrict__ bo_a,
    const float* __restrict__ x_a,  const float* __restrict__ Wr_a,
    const float* __restrict__ Wo_b, const float* __restrict__ bo_b,
    const float* __restrict__ x_b,  const float* __restrict__ Wr_b,
    float* __restrict__ out)
{
    int type = blockIdx.y;   // 0 = a, 1 = b
    const float* Wo = type ? Wo_b : Wo_a;
    const float* bo = type ? bo_b : bo_a;
    const float* x  = type ? x_b  : x_a;
    const float* Wr = type ? Wr_b : Wr_a;
    const float* agg = type ? g_agg1 : g_agg2;   // a's messages come from relation 2
    const float* den = type ? g_den1 : g_den2;
    float* outp = out + (size_t)type * NN * 32;

    __shared__ float afs[32][65];
    __shared__ float xs[32][65];
    __shared__ __align__(16) float WoS[64][32];
    __shared__ __align__(16) float WrS[64][32];
    __shared__ float denS[32][2];
    __shared__ float boS[32];

    int tid = threadIdx.x;
    int nb  = blockIdx.x * 32;

    if (tid < 64) {
        int n2 = nb + (tid >> 1);
        denS[tid >> 1][tid & 1] = (n2 < NN) ? den[n2 * 2 + (tid & 1)] : 0.f;
    }
    if (tid < 32) boS[tid] = bo[tid];
    __syncthreads();

    for (int i = tid; i < 2048; i += 256) {
        int s = i >> 5, o = i & 31;
        WoS[s][o] = Wo[s * 32 + o];
        WrS[s][o] = Wr[s * 32 + o];
        int n2 = nb + (i >> 6), c2 = i & 63;
        float d = denS[i >> 6][c2 >> 5];
        float av = (n2 < NN) ? agg[(size_t)n2 * 64 + c2] : 0.f;
        afs[i >> 6][c2] = (d > 0.f) ? av / d : 0.f;
        xs[i >> 6][c2]  = (n2 < NN) ? x[(size_t)n2 * 64 + c2] : 0.f;
    }
    __syncthreads();

    int nl = tid >> 3, p = tid & 7;
    int n = nb + nl;

    u64 o01 = pack2(boS[p * 4 + 0], boS[p * 4 + 1]);
    u64 o23 = pack2(boS[p * 4 + 2], boS[p * 4 + 3]);
#pragma unroll 8
    for (int k = 0; k < 64; k++) {
        float a  = afs[nl][k];
        float xv = xs[nl][k];
        u64 a2 = pack2(a, a);
        u64 x2 = pack2(xv, xv);
        ulonglong2 wo = *(const ulonglong2*)&WoS[k][p * 4];
        ulonglong2 wr = *(const ulonglong2*)&WrS[k][p * 4];
        o01 = fma2(a2, wo.x, o01); o23 = fma2(a2, wo.y, o23);
        o01 = fma2(x2, wr.x, o01); o23 = fma2(x2, wr.y, o23);
    }
    if (n < NN) {
        float o[4];
        unpack2(o01, o[0], o[1]); unpack2(o23, o[2], o[3]);
        float4* op = (float4*)(outp + (size_t)n * 32 + p * 4);
        op[0] = make_float4(o[0], o[1], o[2], o[3]);
    }
}

// ---------------- launch ----------------
extern "C" void kernel_launch(void* const* d_in, const int* in_sizes, int n_in,
                              void* d_out, int out_size)
{
    const float* x_a    = (const float*)d_in[0];
    const float* x_b    = (const float*)d_in[1];
    const float* ea1    = (const float*)d_in[2];
    const float* ea2    = (const float*)d_in[3];
    const float* Wq_a   = (const float*)d_in[4];
    const float* Wk_a   = (const float*)d_in[5];
    const float* Wv_a   = (const float*)d_in[6];
    const float* Wq_b   = (const float*)d_in[7];
    const float* Wk_b   = (const float*)d_in[8];
    const float* Wv_b   = (const float*)d_in[9];
    const float* emb_a  = (const float*)d_in[10];
    const float* emb_b  = (const float*)d_in[11];
    const float* rel1   = (const float*)d_in[12];
    const float* rel2   = (const float*)d_in[13];
    const float* We     = (const float*)d_in[14];
    const float* a_attn = (const float*)d_in[15];
    const float* Wo_a   = (const float*)d_in[16];
    const float* bo_a   = (const float*)d_in[17];
    const float* Wo_b   = (const float*)d_in[18];
    const float* bo_b   = (const float*)d_in[19];
    const float* Wr_a   = (const float*)d_in[20];
    const float* Wr_b   = (const float*)d_in[21];
    const int*   row1   = (const int*)d_in[22];
    const int*   col1   = (const int*)d_in[23];
    const int*   row2   = (const int*)d_in[24];
    const int*   col2   = (const int*)d_in[25];
    float* out = (float*)d_out;

    cudaFuncSetAttribute(prep_kernel, cudaFuncAttributeMaxDynamicSharedMemorySize, PREP_SMEM);

    prep_kernel<<<ZB + 2 * NB, 256, PREP_SMEM>>>(x_a, Wq_a, Wk_a, Wv_a,
                                                 x_b, Wq_b, Wk_b, Wv_b,
                                                 emb_a, emb_b, rel1, rel2, a_attn);

    edge_kernel<<<2 * EGB, 256>>>(ea1, row1, col1, ea2, row2, col2, We, a_attn);

    dim3 fg((NN + 31) / 32, 2);
    final_kernel<<<fg, 256>>>(Wo_a, bo_a, x_a, Wr_a,
                              Wo_b, bo_b, x_b, Wr_b, out);
}